// round 7
// baseline (speedup 1.0000x reference)
#include <cuda_runtime.h>
#include <cuda_fp16.h>
#include <cstdint>

// ---------------------------------------------------------------------------
// Problem constants
// ---------------------------------------------------------------------------
#define B_BATCH  16
#define L_LEN    320000
#define NFFT     2048
#define HOP      512
#define KFREQ    1025                     // N_FFT/2 + 1
#define T_FRAMES 626
#define M_ROWS   (B_BATCH * T_FRAMES)     // 10016
// Cooley-Tukey: n = n1 + 64*n2 ; Y[m,n1,r] = sum_n2 xw[n1+64n2] w32^{n2 r}
//                X[m,k] = sum_n1 Y[m,n1,k&31] * w2048^{n1 k}
#define S2_NB    72                       // padded stage-2 N (66 used)

// Scratch (__device__ globals — allocation-free rule)
__device__ __half g_y [(size_t)M_ROWS * 4096];        // ~82 MB [m][r][c][n1]
__device__ __half g_b1[32 * 64];                      // [n2][j] j<32:re else im
__device__ __half g_b2[32 * 128 * S2_NB];             // [r][kk][j]
__device__ float  g_win[NFFT];

// ---------------------------------------------------------------------------
// PTX helpers
// ---------------------------------------------------------------------------
__device__ __forceinline__ uint32_t swz128(uint32_t off) {
    return off ^ ((off >> 3) & 0x70);
}
__device__ __forceinline__ void cp16(uint32_t dst, const void* src) {
    asm volatile("cp.async.cg.shared.global [%0], [%1], 16;\n"
                 :: "r"(dst), "l"(src));
}
__device__ __forceinline__ void cp16_pred(uint32_t dst, const void* src, bool ok) {
    int sz = ok ? 16 : 0;
    asm volatile("cp.async.cg.shared.global [%0], [%1], 16, %2;\n"
                 :: "r"(dst), "l"(src), "r"(sz));
}
__device__ __forceinline__ void cp_commit() {
    asm volatile("cp.async.commit_group;\n" ::: "memory");
}
__device__ __forceinline__ void cp_wait0() {
    asm volatile("cp.async.wait_group 0;\n" ::: "memory");
}
__device__ __forceinline__ void cp_wait1() {
    asm volatile("cp.async.wait_group 1;\n" ::: "memory");
}
__device__ __forceinline__ void ldsm_x4(uint32_t* r, uint32_t addr) {
    asm volatile("ldmatrix.sync.aligned.m8n8.x4.shared.b16 {%0,%1,%2,%3}, [%4];\n"
                 : "=r"(r[0]), "=r"(r[1]), "=r"(r[2]), "=r"(r[3]) : "r"(addr));
}
__device__ __forceinline__ void ldsm_x4_t(uint32_t& r0, uint32_t& r1,
                                          uint32_t& r2, uint32_t& r3,
                                          uint32_t addr) {
    asm volatile("ldmatrix.sync.aligned.m8n8.x4.trans.shared.b16 {%0,%1,%2,%3}, [%4];\n"
                 : "=r"(r0), "=r"(r1), "=r"(r2), "=r"(r3) : "r"(addr));
}
__device__ __forceinline__ void ldsm_x2_t(uint32_t& r0, uint32_t& r1,
                                          uint32_t addr) {
    asm volatile("ldmatrix.sync.aligned.m8n8.x2.trans.shared.b16 {%0,%1}, [%2];\n"
                 : "=r"(r0), "=r"(r1) : "r"(addr));
}
__device__ __forceinline__ void mma16816(float* d, const uint32_t* a,
                                         const uint32_t* b) {
    asm volatile(
        "mma.sync.aligned.m16n8k16.row.col.f32.f16.f16.f32 "
        "{%0,%1,%2,%3}, {%4,%5,%6,%7}, {%8,%9}, {%0,%1,%2,%3};\n"
        : "+f"(d[0]), "+f"(d[1]), "+f"(d[2]), "+f"(d[3])
        : "r"(a[0]), "r"(a[1]), "r"(a[2]), "r"(a[3]), "r"(b[0]), "r"(b[1]));
}

// ---------------------------------------------------------------------------
// Tiny preps
// ---------------------------------------------------------------------------
__global__ void prep_win_kernel() {
    int i = blockIdx.x * blockDim.x + threadIdx.x;
    if (i < NFFT) g_win[i] = 0.5f - 0.5f * cospif((float)i / 1024.0f);
}
__global__ void prep_b1_kernel() {
    int i = blockIdx.x * blockDim.x + threadIdx.x;
    if (i >= 32 * 64) return;
    int n2 = i >> 6, j = i & 63;
    int r = j & 31;
    float s, c;
    sincospif((float)(n2 * r) / 16.0f, &s, &c);
    g_b1[i] = __float2half(j < 32 ? c : -s);
}
__global__ void prep_b2_kernel() {
    int i = blockIdx.x * blockDim.x + threadIdx.x;
    const int total = 32 * 128 * S2_NB;
    if (i >= total) return;
    int r   = i / (128 * S2_NB);
    int rem = i - r * (128 * S2_NB);
    int kk  = rem / S2_NB;
    int j   = rem - kk * S2_NB;
    float v = 0.0f;
    if (j < 66) {
        int n1 = kk & 63;
        int k  = (j >> 1) * 32 + r;
        float s, c;
        sincospif((float)(n1 * k) / 1024.0f, &s, &c);
        bool im_in  = kk >= 64;
        bool im_out = (j & 1) != 0;
        v = im_in ? (im_out ? c : s) : (im_out ? -s : c);
    }
    g_b2[i] = __float2half(v);
}

// ---------------------------------------------------------------------------
// Stage 1 (fused framing + DFT32 GEMM): CTA = 4 frames (256 A-rows).
// Direct coalesced LDG of x (no raw smem staging). smem 32KB:
//   sA [0,16K) | sB [16K,20K) | sY aliases [0,32K)
// ---------------------------------------------------------------------------
#define S1_SMEM 32768
__global__ __launch_bounds__(256)
void stage1_kernel(const float* __restrict__ x) {
    extern __shared__ char smem[];
    __half* sY = (__half*)smem;
    const uint32_t sAb = (uint32_t)__cvta_generic_to_shared(smem);
    const uint32_t sBb = sAb + 16384;

    const int tid = threadIdx.x;
    const int wid = tid >> 5, lane = tid & 31;
    const int bm = blockIdx.x;

    // B1 -> smem (SW128)
    {
        int row = tid >> 3, c8 = tid & 7;
        uint4 v = *reinterpret_cast<const uint4*>(&g_b1[row * 64 + c8 * 8]);
        *reinterpret_cast<uint4*>(smem + 16384 +
            swz128((uint32_t)(row * 128 + c8 * 16))) = v;
    }

    // direct load + window + transpose -> sA. thread = (frame, n1).
    {
        const int mloc = tid >> 6, n1 = tid & 63;
        const int m = bm * 4 + mloc;
        const int b = m / T_FRAMES;
        const int tf = m - b * T_FRAMES;
        const float* xb = x + (size_t)b * L_LEN;
        const int base = tf * HOP - 1024 + n1;
#pragma unroll
        for (int c16 = 0; c16 < 4; c16++) {
            __half h[8];
#pragma unroll
            for (int e = 0; e < 8; e++) {
                int n = n1 + 64 * (c16 * 8 + e);
                int jj = base + 64 * (c16 * 8 + e);
                if (jj < 0)           jj = -jj;
                else if (jj >= L_LEN) jj = 2 * (L_LEN - 1) - jj;
                h[e] = __float2half(xb[jj] * g_win[n]);
            }
            int off = tid * 64 + ((c16 ^ (tid & 3)) << 4);
            *reinterpret_cast<uint4*>(smem + off) =
                *reinterpret_cast<uint4*>(h);
        }
    }
    __syncthreads();

    // mma: 8 warps, each 32 rows x 64 cols, K=32
    float acc[2][8][4];
#pragma unroll
    for (int a = 0; a < 2; a++)
#pragma unroll
        for (int bb = 0; bb < 8; bb++)
#pragma unroll
            for (int q = 0; q < 4; q++) acc[a][bb][q] = 0.0f;

#pragma unroll
    for (int ks = 0; ks < 2; ks++) {
        uint32_t af[2][4];
#pragma unroll
        for (int im = 0; im < 2; im++) {
            int row = wid * 32 + im * 16 + (lane & 15);
            int c2 = (ks * 2 + (lane >> 4)) ^ (row & 3);
            ldsm_x4(af[im], sAb + row * 64 + c2 * 16);
        }
        uint32_t bf[8][2];
#pragma unroll
        for (int inp = 0; inp < 4; inp++) {
            int krow = ks * 16 + (lane & 15);
            uint32_t addr = sBb +
                swz128((uint32_t)(krow * 128 + inp * 32 + ((lane >> 4) << 4)));
            uint32_t r0, r1, r2, r3;
            ldsm_x4_t(r0, r1, r2, r3, addr);
            bf[inp * 2][0] = r0;     bf[inp * 2][1] = r1;
            bf[inp * 2 + 1][0] = r2; bf[inp * 2 + 1][1] = r3;
        }
#pragma unroll
        for (int im = 0; im < 2; im++)
#pragma unroll
            for (int in = 0; in < 8; in++)
                mma16816(acc[im][in], af[im], bf[in]);
    }
    __syncthreads();          // sA/sB dead -> sY may overwrite

    // transpose epilogue into sY [m_loc][r*128 + c*64 + n1]
    const int g = lane >> 2, tq = lane & 3;
#pragma unroll
    for (int im = 0; im < 2; im++) {
#pragma unroll
        for (int half = 0; half < 2; half++) {
            int row = wid * 32 + im * 16 + g + half * 8;
            int mloc = row >> 6, n1 = row & 63;
#pragma unroll
            for (int in = 0; in < 8; in++) {
#pragma unroll
                for (int e = 0; e < 2; e++) {
                    int j = in * 8 + tq * 2 + e;
                    sY[mloc * 4096 + (j & 31) * 128 + (j >> 5) * 64 + n1] =
                        __float2half(acc[im][in][half * 2 + e]);
                }
            }
        }
    }
    __syncthreads();

    // coalesced dump: 32KB contiguous
#pragma unroll
    for (int q = 0; q < 8; q++) {
        int ch = q * 256 + tid;
        *reinterpret_cast<uint4*>(&g_y[(size_t)bm * 16384 + ch * 8]) =
            reinterpret_cast<const uint4*>(sY)[ch];
    }
}

// ---------------------------------------------------------------------------
// Fused stage 2 + reorder: CTA = 64 m-rows, loops r=0..31 (double-buffered).
// Per r: [64,128] @ [128,72] GEMM -> sZ[r&7]. Every 8 r's: coalesced
// write-out (8 consecutive r's -> full 32B sectors in out).
// smem: sZ 147,520 | A 2x16,384 | B 2x18,432  = 217,152 B
// ---------------------------------------------------------------------------
#define SLICE_Z  4610                        // 64*72 + 2 (even, bank-staggered)
#define SZ_BYTES (8 * SLICE_Z * 4)           // 147,520
#define A_OFF    SZ_BYTES
#define A_BUF    16384
#define B_OFF    (A_OFF + 2 * A_BUF)
#define B_BUF    18432
#define S2_SMEM  (B_OFF + 2 * B_BUF)         // 217,152
__global__ __launch_bounds__(256)
void stage2_kernel(float* __restrict__ out) {
    extern __shared__ char smem[];
    float* sZ = (float*)smem;
    const uint32_t sb = (uint32_t)__cvta_generic_to_shared(smem);
    const int tid = threadIdx.x;
    const int wid = tid >> 5, lane = tid & 31;
    const int wm = wid & 3;                  // m-warp: 16 rows
    const int wj = wid >> 2;                 // j-warp: 0 -> j[0,40), 1 -> j[40,72)
    const int m0 = blockIdx.x * 64;

    // ---- loader for residue r into buffer s
    auto load_rb = [&](int r, int s) {
        const uint32_t ab = sb + A_OFF + s * A_BUF;
        const uint32_t bb = sb + B_OFF + s * B_BUF;
        // A: 64 rows x 256B (two 128B halves), 1024 cp16
#pragma unroll
        for (int q = 0; q < 4; q++) {
            int i = q * 256 + tid;
            int row = i >> 4, c16 = i & 15;
            int grow = m0 + row;
            int gr = grow < M_ROWS ? grow : 0;
            cp16_pred(ab + (c16 >> 3) * 8192 +
                          swz128((uint32_t)(row * 128 + (c16 & 7) * 16)),
                      &g_y[(size_t)gr * 4096 + r * 128 + c16 * 8],
                      grow < M_ROWS);
        }
        // B: 128 rows x 144B
        {
            int rb = tid & 127;
            const __half* src = &g_b2[((size_t)r * 128 + rb) * S2_NB];
            if (tid < 128) {
#pragma unroll
                for (int cc = 0; cc < 5; cc++)
                    cp16(bb + rb * 144 + cc * 16, src + cc * 8);
            } else {
#pragma unroll
                for (int cc = 5; cc < 9; cc++)
                    cp16(bb + rb * 144 + cc * 16, src + cc * 8);
            }
        }
    };

    load_rb(0, 0);
    cp_commit();

    const size_t imag_base = (size_t)M_ROWS * KFREQ;
    const int u_ = tid & 7, mm_ = (tid >> 3) & 31;

    for (int r = 0; r < 32; r++) {
        if (r + 1 < 32) { load_rb(r + 1, (r + 1) & 1); cp_commit(); cp_wait1(); }
        else            { cp_wait0(); }
        __syncthreads();

        const uint32_t ab = sb + A_OFF + (r & 1) * A_BUF;
        const uint32_t bb = sb + B_OFF + (r & 1) * B_BUF;
        const int jbase = wj * 40;
        const int NT = wj ? 4 : 5;           // n8 tiles this warp

        float acc[5][4];
#pragma unroll
        for (int in = 0; in < 5; in++)
#pragma unroll
            for (int q = 0; q < 4; q++) acc[in][q] = 0.0f;

#pragma unroll
        for (int ks = 0; ks < 8; ks++) {
            uint32_t af[4];
            {
                int row = wm * 16 + (lane & 15);
                int c16 = 2 * ks + (lane >> 4);
                ldsm_x4(af, ab + (c16 >> 3) * 8192 +
                            swz128((uint32_t)(row * 128 + (c16 & 7) * 16)));
            }
            uint32_t bf[5][2];
            int krow = ks * 16 + (lane & 15);
            uint32_t baddr = bb + krow * 144 + jbase * 2 + ((lane >> 4) << 4);
            {
                uint32_t r0, r1, r2, r3;
                ldsm_x4_t(r0, r1, r2, r3, baddr);
                bf[0][0] = r0; bf[0][1] = r1;
                bf[1][0] = r2; bf[1][1] = r3;
                ldsm_x4_t(r0, r1, r2, r3, baddr + 32);
                bf[2][0] = r0; bf[2][1] = r1;
                bf[3][0] = r2; bf[3][1] = r3;
            }
            if (!wj) {
                // tile 4: j 32..39 (x2)
                ldsm_x2_t(bf[4][0], bf[4][1], bb + krow * 144 + 64);
            }
#pragma unroll
            for (int in = 0; in < 5; in++)
                if (in < NT) mma16816(acc[in], af, bf[in]);
        }

        // stash into sZ[r&7]
        {
            const int g = lane >> 2, tq = lane & 3;
            float* dst = sZ + (r & 7) * SLICE_Z;
#pragma unroll
            for (int half = 0; half < 2; half++) {
                int m = wm * 16 + g + half * 8;
#pragma unroll
                for (int in = 0; in < 5; in++) {
                    if (in < NT) {
                        int j0 = jbase + in * 8 + tq * 2;
                        *reinterpret_cast<float2*>(dst + m * S2_NB + j0) =
                            make_float2(acc[in][half * 2],
                                        acc[in][half * 2 + 1]);
                    }
                }
            }
        }

        if ((r & 7) == 7) {
            __syncthreads();
            const int rg = r >> 3;
            // main: k2 0..31, 8 consecutive r -> full 32B sectors
#pragma unroll 2
            for (int mh = 0; mh < 2; mh++) {
                int m = mh * 32 + mm_;
                int row = m0 + m;
                if (row < M_ROWS) {
                    const float* src = sZ + u_ * SLICE_Z + m * S2_NB;
#pragma unroll 4
                    for (int cq = 0; cq < 64; cq++) {
                        int cout = cq >> 5, k2 = cq & 31;
                        out[(cout ? imag_base : 0) + (size_t)row * KFREQ +
                            k2 * 32 + rg * 8 + u_] = src[2 * k2 + cout];
                    }
                }
            }
            // tail: k = 1024 (k2 = 32, r = 0 only)
            if (rg == 0 && tid < 128) {
                int m = tid & 63, cout = tid >> 6;
                int row = m0 + m;
                if (row < M_ROWS)
                    out[(cout ? imag_base : 0) + (size_t)row * KFREQ + 1024] =
                        sZ[m * S2_NB + 64 + cout];
            }
            __syncthreads();
        }
    }
}

// ---------------------------------------------------------------------------
extern "C" void kernel_launch(void* const* d_in, const int* in_sizes, int n_in,
                              void* d_out, int out_size) {
    const float* x = (const float*)d_in[0];
    float* out = (float*)d_out;

    cudaFuncSetAttribute(stage1_kernel,
                         cudaFuncAttributeMaxDynamicSharedMemorySize, S1_SMEM);
    cudaFuncSetAttribute(stage2_kernel,
                         cudaFuncAttributeMaxDynamicSharedMemorySize, S2_SMEM);

    prep_win_kernel<<<8, 256>>>();
    prep_b1_kernel<<<8, 256>>>();
    prep_b2_kernel<<<(32 * 128 * S2_NB + 255) / 256, 256>>>();

    stage1_kernel<<<M_ROWS / 4, 256, S1_SMEM>>>(x);

    stage2_kernel<<<(M_ROWS + 63) / 64, 256, S2_SMEM>>>(out);
}

// round 8
// speedup vs baseline: 1.5860x; 1.5860x over previous
#include <cuda_runtime.h>
#include <cuda_fp16.h>
#include <cstdint>

// ---------------------------------------------------------------------------
// Problem constants
// ---------------------------------------------------------------------------
#define B_BATCH  16
#define L_LEN    320000
#define NFFT     2048
#define HOP      512
#define KFREQ    1025                     // N_FFT/2 + 1
#define T_FRAMES 626
#define M_ROWS   (B_BATCH * T_FRAMES)     // 10016
#define M_PAD    10112                    // 79 * 128
// Cooley-Tukey: n = n1 + 64*n2 ; Y[m,n1,r] = sum_n2 xw[n1+64n2] w32^{n2 r}
//                X[m,k] = sum_n1 Y[m,n1,k&31] * w2048^{n1 k}
#define S2_NB    72                       // padded stage-2 N (66 used)

// Scratch (__device__ globals — allocation-free rule)
__device__ __half g_y [(size_t)M_ROWS * 4096];        // ~82 MB [m][r][c][n1]
__device__ float  g_z [(size_t)32 * M_PAD * S2_NB];   // ~93 MB [r][m][j]
__device__ __half g_b1[32 * 64];                      // [n2][j] j<32:re else im
__device__ __half g_b2[32 * 128 * S2_NB];             // [r][kk][j]
__device__ float  g_win[NFFT];

// ---------------------------------------------------------------------------
// PTX helpers
// ---------------------------------------------------------------------------
__device__ __forceinline__ uint32_t swz128(uint32_t off) {
    return off ^ ((off >> 3) & 0x70);
}
__device__ __forceinline__ void cp16(uint32_t dst, const void* src) {
    asm volatile("cp.async.cg.shared.global [%0], [%1], 16;\n"
                 :: "r"(dst), "l"(src));
}
__device__ __forceinline__ void cp16_pred(uint32_t dst, const void* src, bool ok) {
    int sz = ok ? 16 : 0;
    asm volatile("cp.async.cg.shared.global [%0], [%1], 16, %2;\n"
                 :: "r"(dst), "l"(src), "r"(sz));
}
__device__ __forceinline__ void cp_wait_all() {
    asm volatile("cp.async.commit_group;\n" ::: "memory");
    asm volatile("cp.async.wait_group 0;\n" ::: "memory");
}
__device__ __forceinline__ void ldsm_x4(uint32_t* r, uint32_t addr) {
    asm volatile("ldmatrix.sync.aligned.m8n8.x4.shared.b16 {%0,%1,%2,%3}, [%4];\n"
                 : "=r"(r[0]), "=r"(r[1]), "=r"(r[2]), "=r"(r[3]) : "r"(addr));
}
__device__ __forceinline__ void ldsm_x4_t(uint32_t& r0, uint32_t& r1,
                                          uint32_t& r2, uint32_t& r3,
                                          uint32_t addr) {
    asm volatile("ldmatrix.sync.aligned.m8n8.x4.trans.shared.b16 {%0,%1,%2,%3}, [%4];\n"
                 : "=r"(r0), "=r"(r1), "=r"(r2), "=r"(r3) : "r"(addr));
}
__device__ __forceinline__ void ldsm_x2_t(uint32_t& r0, uint32_t& r1,
                                          uint32_t addr) {
    asm volatile("ldmatrix.sync.aligned.m8n8.x2.trans.shared.b16 {%0,%1}, [%2];\n"
                 : "=r"(r0), "=r"(r1) : "r"(addr));
}
__device__ __forceinline__ void mma16816(float* d, const uint32_t* a,
                                         const uint32_t* b) {
    asm volatile(
        "mma.sync.aligned.m16n8k16.row.col.f32.f16.f16.f32 "
        "{%0,%1,%2,%3}, {%4,%5,%6,%7}, {%8,%9}, {%0,%1,%2,%3};\n"
        : "+f"(d[0]), "+f"(d[1]), "+f"(d[2]), "+f"(d[3])
        : "r"(a[0]), "r"(a[1]), "r"(a[2]), "r"(a[3]), "r"(b[0]), "r"(b[1]));
}

// ---------------------------------------------------------------------------
// Merged prep: window + B1 + B2 in one launch
// ---------------------------------------------------------------------------
__global__ void prep_all_kernel() {
    int i = blockIdx.x * blockDim.x + threadIdx.x;
    // B2 part (largest): 32*128*72 = 294912
    const int total_b2 = 32 * 128 * S2_NB;
    if (i < total_b2) {
        int r   = i / (128 * S2_NB);
        int rem = i - r * (128 * S2_NB);
        int kk  = rem / S2_NB;
        int j   = rem - kk * S2_NB;
        float v = 0.0f;
        if (j < 66) {
            int n1 = kk & 63;
            int k  = (j >> 1) * 32 + r;
            float s, c;
            sincospif((float)(n1 * k) / 1024.0f, &s, &c);
            bool im_in  = kk >= 64;
            bool im_out = (j & 1) != 0;
            v = im_in ? (im_out ? c : s) : (im_out ? -s : c);
        }
        g_b2[i] = __float2half(v);
    }
    if (i < NFFT)
        g_win[i] = 0.5f - 0.5f * cospif((float)i / 1024.0f);
    if (i >= NFFT && i < NFFT + 32 * 64) {
        int t = i - NFFT;
        int n2 = t >> 6, j = t & 63;
        int r = j & 31;
        float s, c;
        sincospif((float)(n2 * r) / 16.0f, &s, &c);
        g_b1[t] = __float2half(j < 32 ? c : -s);
    }
}

// ---------------------------------------------------------------------------
// Stage 1 (fused framing + DFT32 GEMM): CTA = 4 frames (256 A-rows).
// Direct coalesced LDG of x. smem phase A: sA 16K | sB 4K.
// Phase B (alias): sY padded [mloc][r][c][n1], r-slice 136 halves -> 34816 B.
// ---------------------------------------------------------------------------
#define SY_RSLICE 136                     // 128 + 8 pad halves per r
#define SY_MLOC   (32 * SY_RSLICE)        // 4352 halves per frame
#define S1_SMEM   (4 * SY_MLOC * 2)       // 34816 B
__global__ __launch_bounds__(256)
void stage1_kernel(const float* __restrict__ x) {
    extern __shared__ char smem[];
    __half* sY = (__half*)smem;
    const uint32_t sAb = (uint32_t)__cvta_generic_to_shared(smem);
    const uint32_t sBb = sAb + 16384;

    const int tid = threadIdx.x;
    const int wid = tid >> 5, lane = tid & 31;
    const int bm = blockIdx.x;

    // B1 -> smem (SW128)
    {
        int row = tid >> 3, c8 = tid & 7;
        uint4 v = *reinterpret_cast<const uint4*>(&g_b1[row * 64 + c8 * 8]);
        *reinterpret_cast<uint4*>(smem + 16384 +
            swz128((uint32_t)(row * 128 + c8 * 16))) = v;
    }

    // direct load + window + transpose -> sA. thread = (frame, n1).
    {
        const int mloc = tid >> 6, n1 = tid & 63;
        const int m = bm * 4 + mloc;
        const int b = m / T_FRAMES;
        const int tf = m - b * T_FRAMES;
        const float* xb = x + (size_t)b * L_LEN;
        const int base = tf * HOP - 1024 + n1;
#pragma unroll
        for (int c16 = 0; c16 < 4; c16++) {
            __half h[8];
#pragma unroll
            for (int e = 0; e < 8; e++) {
                int n = n1 + 64 * (c16 * 8 + e);
                int jj = base + 64 * (c16 * 8 + e);
                if (jj < 0)           jj = -jj;
                else if (jj >= L_LEN) jj = 2 * (L_LEN - 1) - jj;
                h[e] = __float2half(xb[jj] * g_win[n]);
            }
            int off = tid * 64 + ((c16 ^ (tid & 3)) << 4);
            *reinterpret_cast<uint4*>(smem + off) =
                *reinterpret_cast<uint4*>(h);
        }
    }
    __syncthreads();

    // mma: 8 warps, each 32 rows x 64 cols, K=32
    float acc[2][8][4];
#pragma unroll
    for (int a = 0; a < 2; a++)
#pragma unroll
        for (int bb = 0; bb < 8; bb++)
#pragma unroll
            for (int q = 0; q < 4; q++) acc[a][bb][q] = 0.0f;

#pragma unroll
    for (int ks = 0; ks < 2; ks++) {
        uint32_t af[2][4];
#pragma unroll
        for (int im = 0; im < 2; im++) {
            int row = wid * 32 + im * 16 + (lane & 15);
            int c2 = (ks * 2 + (lane >> 4)) ^ (row & 3);
            ldsm_x4(af[im], sAb + row * 64 + c2 * 16);
        }
        uint32_t bf[8][2];
#pragma unroll
        for (int inp = 0; inp < 4; inp++) {
            int krow = ks * 16 + (lane & 15);
            uint32_t addr = sBb +
                swz128((uint32_t)(krow * 128 + inp * 32 + ((lane >> 4) << 4)));
            uint32_t r0, r1, r2, r3;
            ldsm_x4_t(r0, r1, r2, r3, addr);
            bf[inp * 2][0] = r0;     bf[inp * 2][1] = r1;
            bf[inp * 2 + 1][0] = r2; bf[inp * 2 + 1][1] = r3;
        }
#pragma unroll
        for (int im = 0; im < 2; im++)
#pragma unroll
            for (int in = 0; in < 8; in++)
                mma16816(acc[im][in], af[im], bf[in]);
    }
    __syncthreads();          // sA/sB dead -> sY may overwrite

    // transpose epilogue into padded sY [mloc][r*136 + c*64 + n1]
    const int g = lane >> 2, tq = lane & 3;
#pragma unroll
    for (int im = 0; im < 2; im++) {
#pragma unroll
        for (int half = 0; half < 2; half++) {
            int row = wid * 32 + im * 16 + g + half * 8;
            int mloc = row >> 6, n1 = row & 63;
#pragma unroll
            for (int in = 0; in < 8; in++) {
#pragma unroll
                for (int e = 0; e < 2; e++) {
                    int j = in * 8 + tq * 2 + e;
                    sY[mloc * SY_MLOC + (j & 31) * SY_RSLICE + (j >> 5) * 64 +
                       n1] = __float2half(acc[im][in][half * 2 + e]);
                }
            }
        }
    }
    __syncthreads();

    // coalesced dump to unpadded g_y layout [m][r*128 + c*64 + n1]
#pragma unroll
    for (int q = 0; q < 8; q++) {
        int ch = q * 256 + tid;              // 2048 chunks of 8 halves
        int l = ch * 8;
        int mloc = l >> 12;
        int rem = l & 4095;
        int r = rem >> 7, rem2 = rem & 127;
        const uint4 v = *reinterpret_cast<const uint4*>(
            &sY[mloc * SY_MLOC + r * SY_RSLICE + rem2]);
        *reinterpret_cast<uint4*>(&g_y[(size_t)bm * 16384 + l]) = v;
    }
}

// ---------------------------------------------------------------------------
// Stage 2: per residue r: Z_r = Yr[M,128] @ B2_r[128,72] -> g_z coalesced
// grid (79, 32), CTA 128 thr, warp 32x72, one-shot K=128.
// ---------------------------------------------------------------------------
#define S2_SMEM (32768 + 128 * 144)
__global__ __launch_bounds__(128)
void stage2_kernel() {
    extern __shared__ char smem[];
    const uint32_t sAb = (uint32_t)__cvta_generic_to_shared(smem);
    const uint32_t sBb = sAb + 32768;
    const int tid = threadIdx.x;
    const int wid = tid >> 5, lane = tid & 31;
    const int bm = blockIdx.x;
    const int rblk = blockIdx.y;

#pragma unroll
    for (int q = 0; q < 16; q++) {
        int i = q * 128 + tid;
        int row = i >> 4, c16 = i & 15;
        int h = c16 >> 3, c8 = c16 & 7;
        int grow = bm * 128 + row;
        int gr = grow < M_ROWS ? grow : 0;
        cp16_pred(sAb + h * 16384 + swz128((uint32_t)(row * 128 + c8 * 16)),
                  &g_y[(size_t)gr * 4096 + rblk * 128 + c16 * 8],
                  grow < M_ROWS);
    }
    {
        const __half* src = &g_b2[(size_t)rblk * 128 * S2_NB + tid * S2_NB];
#pragma unroll
        for (int cc = 0; cc < 9; cc++)
            cp16(sBb + tid * 144 + cc * 16, src + cc * 8);
    }
    cp_wait_all();
    __syncthreads();

    float acc[2][9][4];
#pragma unroll
    for (int a = 0; a < 2; a++)
#pragma unroll
        for (int bb = 0; bb < 9; bb++)
#pragma unroll
            for (int q = 0; q < 4; q++) acc[a][bb][q] = 0.0f;

#pragma unroll
    for (int ks = 0; ks < 8; ks++) {
        uint32_t af[2][4];
#pragma unroll
        for (int im = 0; im < 2; im++) {
            int row = wid * 32 + im * 16 + (lane & 15);
            int c16 = 2 * ks + (lane >> 4);
            int h = c16 >> 3, c8 = c16 & 7;
            ldsm_x4(af[im], sAb + h * 16384 +
                            swz128((uint32_t)(row * 128 + c8 * 16)));
        }
        uint32_t bf[9][2];
#pragma unroll
        for (int inp = 0; inp < 4; inp++) {
            int krow = ks * 16 + (lane & 15);
            uint32_t addr = sBb + krow * 144 + inp * 32 + ((lane >> 4) << 4);
            uint32_t r0, r1, r2, r3;
            ldsm_x4_t(r0, r1, r2, r3, addr);
            bf[inp * 2][0] = r0;     bf[inp * 2][1] = r1;
            bf[inp * 2 + 1][0] = r2; bf[inp * 2 + 1][1] = r3;
        }
        {
            int krow = ks * 16 + (lane & 15);
            ldsm_x2_t(bf[8][0], bf[8][1], sBb + krow * 144 + 128);
        }
#pragma unroll
        for (int im = 0; im < 2; im++)
#pragma unroll
            for (int in = 0; in < 9; in++)
                mma16816(acc[im][in], af[im], bf[in]);
    }

    // coalesced float2 stores to g_z[rblk][grow][j]
    const int g = lane >> 2, tq = lane & 3;
#pragma unroll
    for (int im = 0; im < 2; im++) {
#pragma unroll
        for (int half = 0; half < 2; half++) {
            int grow = bm * 128 + wid * 32 + im * 16 + g + half * 8;
            float* dst = &g_z[((size_t)rblk * M_PAD + grow) * S2_NB];
#pragma unroll
            for (int in = 0; in < 9; in++) {
                int j0 = in * 8 + tq * 2;
                *reinterpret_cast<float2*>(dst + j0) =
                    make_float2(acc[im][in][half * 2],
                                acc[im][in][half * 2 + 1]);
            }
        }
    }
}

// ---------------------------------------------------------------------------
// Reorder: g_z[r][m][j] -> out (real/imag planes), fully coalesced both sides.
// CTA = 8 output rows; smem slices padded to 577 floats (bank-safe).
// ---------------------------------------------------------------------------
#define RB      8
#define SLICE   577                              // 8*72 + 1 (odd)
#define RD_SMEM (32 * SLICE * 4)                 // 73856 B
__global__ __launch_bounds__(256)
void reorder_kernel(float* __restrict__ out) {
    extern __shared__ float s[];
    const int tid = threadIdx.x;
    const int m0 = blockIdx.x * RB;

    // load 32 slices x (8 x 72) floats, coalesced float4
#pragma unroll
    for (int q = 0; q < 18; q++) {
        int ch = q * 256 + tid;                  // 4608 chunks
        int r = ch / 144, w = ch - r * 144;
        float4 v = *reinterpret_cast<const float4*>(
            &g_z[((size_t)r * M_PAD + m0) * S2_NB + w * 4]);
        float* dst = &s[r * SLICE + w * 4];
        dst[0] = v.x; dst[1] = v.y; dst[2] = v.z; dst[3] = v.w;
    }
    __syncthreads();

    const size_t imag_base = (size_t)M_ROWS * KFREQ;
#pragma unroll 4
    for (int q = 0; q < 65; q++) {
        int o = q * 256 + tid;
        if (o < RB * 2050) {
            int mm = o / 2050;
            int rem = o - mm * 2050;
            int cout = rem / 1025;
            int k = rem - cout * 1025;
            int r = k & 31, k2 = k >> 5;
            float v = s[r * SLICE + mm * S2_NB + 2 * k2 + cout];
            out[(cout ? imag_base : 0) + (size_t)(m0 + mm) * KFREQ + k] = v;
        }
    }
}

// ---------------------------------------------------------------------------
extern "C" void kernel_launch(void* const* d_in, const int* in_sizes, int n_in,
                              void* d_out, int out_size) {
    const float* x = (const float*)d_in[0];
    float* out = (float*)d_out;

    cudaFuncSetAttribute(stage1_kernel,
                         cudaFuncAttributeMaxDynamicSharedMemorySize, S1_SMEM);
    cudaFuncSetAttribute(stage2_kernel,
                         cudaFuncAttributeMaxDynamicSharedMemorySize, S2_SMEM);
    cudaFuncSetAttribute(reorder_kernel,
                         cudaFuncAttributeMaxDynamicSharedMemorySize, RD_SMEM);

    prep_all_kernel<<<(32 * 128 * S2_NB + 255) / 256, 256>>>();

    stage1_kernel<<<M_ROWS / 4, 256, S1_SMEM>>>(x);

    dim3 g2((M_ROWS + 127) / 128, 32);           // 79 x 32
    stage2_kernel<<<g2, 128, S2_SMEM>>>();

    reorder_kernel<<<M_ROWS / RB, 256, RD_SMEM>>>(out);
}

// round 9
// speedup vs baseline: 1.8040x; 1.1375x over previous
#include <cuda_runtime.h>
#include <cuda_fp16.h>
#include <cstdint>

// ---------------------------------------------------------------------------
// Problem constants
// ---------------------------------------------------------------------------
#define B_BATCH  16
#define L_LEN    320000
#define NFFT     2048
#define HOP      512
#define KFREQ    1025                     // N_FFT/2 + 1
#define T_FRAMES 626
#define M_ROWS   (B_BATCH * T_FRAMES)     // 10016
#define M_PAD    10112                    // 79 * 128
// Cooley-Tukey: n = n1 + 64*n2 ; Y[m,n1,r] = sum_n2 xw[n1+64n2] w32^{n2 r}
//                X[m,k] = sum_n1 Y[m,n1,k&31] * w2048^{n1 k}
#define S2_NB    72                       // padded stage-2 N (66 used)

// Scratch (__device__ globals — allocation-free rule)
__device__ __half g_y [(size_t)M_ROWS * 4096];        // ~82 MB [m][r][c][n1]
__device__ float  g_z [(size_t)32 * M_PAD * S2_NB];   // ~93 MB [r][m][j]
__device__ __half g_b1[32 * 64];                      // [n2][j] j<32:re else im
__device__ __half g_b2[32 * 128 * S2_NB];             // [r][kk][j]
__device__ float  g_win[NFFT];

// ---------------------------------------------------------------------------
// PTX helpers
// ---------------------------------------------------------------------------
__device__ __forceinline__ uint32_t swz128(uint32_t off) {
    return off ^ ((off >> 3) & 0x70);
}
__device__ __forceinline__ void cp16(uint32_t dst, const void* src) {
    asm volatile("cp.async.cg.shared.global [%0], [%1], 16;\n"
                 :: "r"(dst), "l"(src));
}
__device__ __forceinline__ void cp16_pred(uint32_t dst, const void* src, bool ok) {
    int sz = ok ? 16 : 0;
    asm volatile("cp.async.cg.shared.global [%0], [%1], 16, %2;\n"
                 :: "r"(dst), "l"(src), "r"(sz));
}
__device__ __forceinline__ void cp_wait_all() {
    asm volatile("cp.async.commit_group;\n" ::: "memory");
    asm volatile("cp.async.wait_group 0;\n" ::: "memory");
}
__device__ __forceinline__ void ldsm_x4(uint32_t* r, uint32_t addr) {
    asm volatile("ldmatrix.sync.aligned.m8n8.x4.shared.b16 {%0,%1,%2,%3}, [%4];\n"
                 : "=r"(r[0]), "=r"(r[1]), "=r"(r[2]), "=r"(r[3]) : "r"(addr));
}
__device__ __forceinline__ void ldsm_x4_t(uint32_t& r0, uint32_t& r1,
                                          uint32_t& r2, uint32_t& r3,
                                          uint32_t addr) {
    asm volatile("ldmatrix.sync.aligned.m8n8.x4.trans.shared.b16 {%0,%1,%2,%3}, [%4];\n"
                 : "=r"(r0), "=r"(r1), "=r"(r2), "=r"(r3) : "r"(addr));
}
__device__ __forceinline__ void ldsm_x2_t(uint32_t& r0, uint32_t& r1,
                                          uint32_t addr) {
    asm volatile("ldmatrix.sync.aligned.m8n8.x2.trans.shared.b16 {%0,%1}, [%2];\n"
                 : "=r"(r0), "=r"(r1) : "r"(addr));
}
__device__ __forceinline__ void mma16816(float* d, const uint32_t* a,
                                         const uint32_t* b) {
    asm volatile(
        "mma.sync.aligned.m16n8k16.row.col.f32.f16.f16.f32 "
        "{%0,%1,%2,%3}, {%4,%5,%6,%7}, {%8,%9}, {%0,%1,%2,%3};\n"
        : "+f"(d[0]), "+f"(d[1]), "+f"(d[2]), "+f"(d[3])
        : "r"(a[0]), "r"(a[1]), "r"(a[2]), "r"(a[3]), "r"(b[0]), "r"(b[1]));
}

// ---------------------------------------------------------------------------
// Merged prep: window + B1 + B2 in one launch
// ---------------------------------------------------------------------------
__global__ void prep_all_kernel() {
    int i = blockIdx.x * blockDim.x + threadIdx.x;
    const int total_b2 = 32 * 128 * S2_NB;
    if (i < total_b2) {
        int r   = i / (128 * S2_NB);
        int rem = i - r * (128 * S2_NB);
        int kk  = rem / S2_NB;
        int j   = rem - kk * S2_NB;
        float v = 0.0f;
        if (j < 66) {
            int n1 = kk & 63;
            int k  = (j >> 1) * 32 + r;
            float s, c;
            sincospif((float)(n1 * k) / 1024.0f, &s, &c);
            bool im_in  = kk >= 64;
            bool im_out = (j & 1) != 0;
            v = im_in ? (im_out ? c : s) : (im_out ? -s : c);
        }
        g_b2[i] = __float2half(v);
    }
    if (i < NFFT)
        g_win[i] = 0.5f - 0.5f * cospif((float)i / 1024.0f);
    if (i >= NFFT && i < NFFT + 32 * 64) {
        int t = i - NFFT;
        int n2 = t >> 6, j = t & 63;
        int r = j & 31;
        float s, c;
        sincospif((float)(n2 * r) / 16.0f, &s, &c);
        g_b1[t] = __float2half(j < 32 ? c : -s);
    }
}

// ---------------------------------------------------------------------------
// Stage 1 (fused framing + DFT32 GEMM): CTA = 4 frames (256 A-rows).
// ---------------------------------------------------------------------------
#define SY_RSLICE 136
#define SY_MLOC   (32 * SY_RSLICE)
#define S1_SMEM   (4 * SY_MLOC * 2)       // 34816 B
__global__ __launch_bounds__(256)
void stage1_kernel(const float* __restrict__ x) {
    extern __shared__ char smem[];
    __half* sY = (__half*)smem;
    const uint32_t sAb = (uint32_t)__cvta_generic_to_shared(smem);
    const uint32_t sBb = sAb + 16384;

    const int tid = threadIdx.x;
    const int wid = tid >> 5, lane = tid & 31;
    const int bm = blockIdx.x;

    // B1 -> smem (SW128)
    {
        int row = tid >> 3, c8 = tid & 7;
        uint4 v = *reinterpret_cast<const uint4*>(&g_b1[row * 64 + c8 * 8]);
        *reinterpret_cast<uint4*>(smem + 16384 +
            swz128((uint32_t)(row * 128 + c8 * 16))) = v;
    }

    // direct load + window + transpose -> sA. thread = (frame, n1).
    {
        const int mloc = tid >> 6, n1 = tid & 63;
        const int m = bm * 4 + mloc;
        const int b = m / T_FRAMES;
        const int tf = m - b * T_FRAMES;
        const float* xb = x + (size_t)b * L_LEN;
        const int base = tf * HOP - 1024 + n1;
#pragma unroll
        for (int c16 = 0; c16 < 4; c16++) {
            __half h[8];
#pragma unroll
            for (int e = 0; e < 8; e++) {
                int n = n1 + 64 * (c16 * 8 + e);
                int jj = base + 64 * (c16 * 8 + e);
                if (jj < 0)           jj = -jj;
                else if (jj >= L_LEN) jj = 2 * (L_LEN - 1) - jj;
                h[e] = __float2half(xb[jj] * g_win[n]);
            }
            int off = tid * 64 + ((c16 ^ (tid & 3)) << 4);
            *reinterpret_cast<uint4*>(smem + off) =
                *reinterpret_cast<uint4*>(h);
        }
    }
    __syncthreads();

    float acc[2][8][4];
#pragma unroll
    for (int a = 0; a < 2; a++)
#pragma unroll
        for (int bb = 0; bb < 8; bb++)
#pragma unroll
            for (int q = 0; q < 4; q++) acc[a][bb][q] = 0.0f;

#pragma unroll
    for (int ks = 0; ks < 2; ks++) {
        uint32_t af[2][4];
#pragma unroll
        for (int im = 0; im < 2; im++) {
            int row = wid * 32 + im * 16 + (lane & 15);
            int c2 = (ks * 2 + (lane >> 4)) ^ (row & 3);
            ldsm_x4(af[im], sAb + row * 64 + c2 * 16);
        }
        uint32_t bf[8][2];
#pragma unroll
        for (int inp = 0; inp < 4; inp++) {
            int krow = ks * 16 + (lane & 15);
            uint32_t addr = sBb +
                swz128((uint32_t)(krow * 128 + inp * 32 + ((lane >> 4) << 4)));
            uint32_t r0, r1, r2, r3;
            ldsm_x4_t(r0, r1, r2, r3, addr);
            bf[inp * 2][0] = r0;     bf[inp * 2][1] = r1;
            bf[inp * 2 + 1][0] = r2; bf[inp * 2 + 1][1] = r3;
        }
#pragma unroll
        for (int im = 0; im < 2; im++)
#pragma unroll
            for (int in = 0; in < 8; in++)
                mma16816(acc[im][in], af[im], bf[in]);
    }
    __syncthreads();

    // transpose epilogue into padded sY [mloc][r*136 + c*64 + n1]
    const int g = lane >> 2, tq = lane & 3;
#pragma unroll
    for (int im = 0; im < 2; im++) {
#pragma unroll
        for (int half = 0; half < 2; half++) {
            int row = wid * 32 + im * 16 + g + half * 8;
            int mloc = row >> 6, n1 = row & 63;
#pragma unroll
            for (int in = 0; in < 8; in++) {
#pragma unroll
                for (int e = 0; e < 2; e++) {
                    int j = in * 8 + tq * 2 + e;
                    sY[mloc * SY_MLOC + (j & 31) * SY_RSLICE + (j >> 5) * 64 +
                       n1] = __float2half(acc[im][in][half * 2 + e]);
                }
            }
        }
    }
    __syncthreads();

    // coalesced dump to unpadded g_y layout [m][r*128 + c*64 + n1]
#pragma unroll
    for (int q = 0; q < 8; q++) {
        int ch = q * 256 + tid;
        int l = ch * 8;
        int mloc = l >> 12;
        int rem = l & 4095;
        int r = rem >> 7, rem2 = rem & 127;
        const uint4 v = *reinterpret_cast<const uint4*>(
            &sY[mloc * SY_MLOC + r * SY_RSLICE + rem2]);
        *reinterpret_cast<uint4*>(&g_y[(size_t)bm * 16384 + l]) = v;
    }
}

// ---------------------------------------------------------------------------
// Stage 2: per residue r: Z_r = Yr[M,128] @ B2_r[128,72] -> g_z coalesced
// ---------------------------------------------------------------------------
#define S2_SMEM (32768 + 128 * 144)
__global__ __launch_bounds__(128)
void stage2_kernel() {
    extern __shared__ char smem[];
    const uint32_t sAb = (uint32_t)__cvta_generic_to_shared(smem);
    const uint32_t sBb = sAb + 32768;
    const int tid = threadIdx.x;
    const int wid = tid >> 5, lane = tid & 31;
    const int bm = blockIdx.x;
    const int rblk = blockIdx.y;

#pragma unroll
    for (int q = 0; q < 16; q++) {
        int i = q * 128 + tid;
        int row = i >> 4, c16 = i & 15;
        int h = c16 >> 3, c8 = c16 & 7;
        int grow = bm * 128 + row;
        int gr = grow < M_ROWS ? grow : 0;
        cp16_pred(sAb + h * 16384 + swz128((uint32_t)(row * 128 + c8 * 16)),
                  &g_y[(size_t)gr * 4096 + rblk * 128 + c16 * 8],
                  grow < M_ROWS);
    }
    {
        const __half* src = &g_b2[(size_t)rblk * 128 * S2_NB + tid * S2_NB];
#pragma unroll
        for (int cc = 0; cc < 9; cc++)
            cp16(sBb + tid * 144 + cc * 16, src + cc * 8);
    }
    cp_wait_all();
    __syncthreads();

    float acc[2][9][4];
#pragma unroll
    for (int a = 0; a < 2; a++)
#pragma unroll
        for (int bb = 0; bb < 9; bb++)
#pragma unroll
            for (int q = 0; q < 4; q++) acc[a][bb][q] = 0.0f;

#pragma unroll
    for (int ks = 0; ks < 8; ks++) {
        uint32_t af[2][4];
#pragma unroll
        for (int im = 0; im < 2; im++) {
            int row = wid * 32 + im * 16 + (lane & 15);
            int c16 = 2 * ks + (lane >> 4);
            int h = c16 >> 3, c8 = c16 & 7;
            ldsm_x4(af[im], sAb + h * 16384 +
                            swz128((uint32_t)(row * 128 + c8 * 16)));
        }
        uint32_t bf[9][2];
#pragma unroll
        for (int inp = 0; inp < 4; inp++) {
            int krow = ks * 16 + (lane & 15);
            uint32_t addr = sBb + krow * 144 + inp * 32 + ((lane >> 4) << 4);
            uint32_t r0, r1, r2, r3;
            ldsm_x4_t(r0, r1, r2, r3, addr);
            bf[inp * 2][0] = r0;     bf[inp * 2][1] = r1;
            bf[inp * 2 + 1][0] = r2; bf[inp * 2 + 1][1] = r3;
        }
        {
            int krow = ks * 16 + (lane & 15);
            ldsm_x2_t(bf[8][0], bf[8][1], sBb + krow * 144 + 128);
        }
#pragma unroll
        for (int im = 0; im < 2; im++)
#pragma unroll
            for (int in = 0; in < 9; in++)
                mma16816(acc[im][in], af[im], bf[in]);
    }

    const int g = lane >> 2, tq = lane & 3;
#pragma unroll
    for (int im = 0; im < 2; im++) {
#pragma unroll
        for (int half = 0; half < 2; half++) {
            int grow = bm * 128 + wid * 32 + im * 16 + g + half * 8;
            float* dst = &g_z[((size_t)rblk * M_PAD + grow) * S2_NB];
#pragma unroll
            for (int in = 0; in < 9; in++) {
                int j0 = in * 8 + tq * 2;
                *reinterpret_cast<float2*>(dst + j0) =
                    make_float2(acc[im][in][half * 2],
                                acc[im][in][half * 2 + 1]);
            }
        }
    }
}

// ---------------------------------------------------------------------------
// Reorder: g_z[r][m][j] -> out, div-free write phase.
// CTA = 8 output rows; smem slices padded to 577 floats.
// ---------------------------------------------------------------------------
#define RB      8
#define SLICE   577                              // 8*72 + 1 (odd)
#define RD_SMEM (32 * SLICE * 4)                 // 73856 B
__global__ __launch_bounds__(256)
void reorder_kernel(float* __restrict__ out) {
    extern __shared__ float s[];
    const int tid = threadIdx.x;
    const int m0 = blockIdx.x * RB;

    // load 32 slices x (8 x 72) floats, coalesced float4
#pragma unroll
    for (int q = 0; q < 18; q++) {
        int ch = q * 256 + tid;                  // 4608 chunks
        int r = ch / 144, w = ch - r * 144;
        float4 v = *reinterpret_cast<const float4*>(
            &g_z[((size_t)r * M_PAD + m0) * S2_NB + w * 4]);
        float* dst = &s[r * SLICE + w * 4];
        dst[0] = v.x; dst[1] = v.y; dst[2] = v.z; dst[3] = v.w;
    }
    __syncthreads();

    // div-free write: k = q*256 + tid ; r = k&31 ; k2 = k>>5
    // bank(r*577 + ...) ≈ (r + c) & 31 -> conflict-free across lanes
    const size_t imag_base = (size_t)M_ROWS * KFREQ;
#pragma unroll
    for (int mm = 0; mm < RB; mm++) {
        const int row = m0 + mm;                 // M_ROWS % RB == 0 -> in range
        const float* srow = s + mm * S2_NB;
        float* ore = out + (size_t)row * KFREQ;
        float* oim = out + imag_base + (size_t)row * KFREQ;
#pragma unroll
        for (int q = 0; q < 5; q++) {
            int k = q * 256 + tid;
            if (k < KFREQ) {
                int r = k & 31, k2 = k >> 5;
                const float* p = srow + r * SLICE + 2 * k2;
                ore[k] = p[0];
                oim[k] = p[1];
            }
        }
    }
}

// ---------------------------------------------------------------------------
extern "C" void kernel_launch(void* const* d_in, const int* in_sizes, int n_in,
                              void* d_out, int out_size) {
    const float* x = (const float*)d_in[0];
    float* out = (float*)d_out;

    cudaFuncSetAttribute(stage1_kernel,
                         cudaFuncAttributeMaxDynamicSharedMemorySize, S1_SMEM);
    cudaFuncSetAttribute(stage2_kernel,
                         cudaFuncAttributeMaxDynamicSharedMemorySize, S2_SMEM);
    cudaFuncSetAttribute(reorder_kernel,
                         cudaFuncAttributeMaxDynamicSharedMemorySize, RD_SMEM);

    prep_all_kernel<<<(32 * 128 * S2_NB + 255) / 256, 256>>>();

    stage1_kernel<<<M_ROWS / 4, 256, S1_SMEM>>>(x);

    dim3 g2((M_ROWS + 127) / 128, 32);           // 79 x 32
    stage2_kernel<<<g2, 128, S2_SMEM>>>();

    reorder_kernel<<<M_ROWS / RB, 256, RD_SMEM>>>(out);
}